// round 1
// baseline (speedup 1.0000x reference)
#include <cuda_runtime.h>
#include <cuda_bf16.h>
#include <math.h>

// ---------------- problem constants ----------------
#define NFEAT 256
#define NHID  256
#define NHEADS 4
#define DH 64
#define ALPHA 0.2f
#define BB 16
#define TT 6
#define NN 128
#define NTOT (BB*TT*NN)      // 12288
#define DEG 16
#define EDGES (NTOT*DEG)     // 196608

// ---------------- scratch (device globals, no allocation) ----------------
__device__ float g_h[NTOT*NHID];
__device__ float g_Wh[NTOT*NHID];
__device__ float g_msg[NTOT*NHID];
__device__ float g_es[NTOT*4];
__device__ float g_ed[NTOT*4];
__device__ float g_gm[NTOT*768];     // msg @ [Wz|Wr|Wn]
__device__ float g_gh[NTOT*512];     // h   @ [Uz|Ur]
__device__ float g_z[NTOT*NHID];
__device__ float g_rh[NTOT*NHID];
__device__ float g_rn[NTOT*NHID];    // (r*h) @ Un
__device__ float g_Wcat[256*768];
__device__ float g_Ucat[256*512];
__device__ int   g_cnt[NTOT];
__device__ int   g_off[NTOT+1];
__device__ int   g_fill[NTOT];
__device__ int   g_csr[EDGES];
__device__ float g_ascore[NTOT];
__device__ float g_pooled[BB*TT*NHID];

// ---------------- small helpers ----------------
__device__ __forceinline__ float lrelu(float x){ return x >= 0.f ? x : ALPHA * x; }

// ---------------- weight concat ----------------
__global__ void concat_kernel(const float* __restrict__ Wz, const float* __restrict__ Uz,
                              const float* __restrict__ Wr, const float* __restrict__ Ur,
                              const float* __restrict__ Wn) {
    int i = blockIdx.x * blockDim.x + threadIdx.x;
    if (i >= 256*256) return;
    int k = i >> 8, j = i & 255;
    g_Wcat[k*768 + j]       = Wz[i];
    g_Wcat[k*768 + 256 + j] = Wr[i];
    g_Wcat[k*768 + 512 + j] = Wn[i];
    g_Ucat[k*512 + j]       = Uz[i];
    g_Ucat[k*512 + 256 + j] = Ur[i];
}

// ---------------- h init: feat = (emb*nmask)[nodeidx] ----------------
__global__ void init_kernel(const float* __restrict__ emb, const float* __restrict__ nmask,
                            const int* __restrict__ nodeidx) {
    int idx = blockIdx.x * blockDim.x + threadIdx.x;
    if (idx >= NTOT*NHID) return;
    int v = idx >> 8, d = idx & 255;
    int s = nodeidx[v];
    g_h[idx] = emb[s*NFEAT + d] * nmask[s];
}

// ---------------- CSR build ----------------
__global__ void zero_cnt_kernel() {
    int i = blockIdx.x * blockDim.x + threadIdx.x;
    if (i < NTOT) g_cnt[i] = 0;
}
__global__ void count_kernel(const int* __restrict__ dst) {
    int e = blockIdx.x * blockDim.x + threadIdx.x;
    if (e < EDGES) atomicAdd(&g_cnt[dst[e]], 1);
}
__global__ void scan_kernel() {  // 1 block, 1024 threads
    __shared__ int s[1024];
    __shared__ int carry;
    int tid = threadIdx.x;
    if (tid == 0) { carry = 0; g_off[0] = 0; }
    __syncthreads();
    for (int c = 0; c < NTOT/1024; c++) {
        int i = c*1024 + tid;
        s[tid] = g_cnt[i];
        __syncthreads();
        for (int d = 1; d < 1024; d <<= 1) {
            int t = (tid >= d) ? s[tid-d] : 0;
            __syncthreads();
            s[tid] += t;
            __syncthreads();
        }
        g_off[i+1] = carry + s[tid];
        __syncthreads();
        if (tid == 0) carry += s[1023];
        __syncthreads();
    }
}
__global__ void fill_kernel() {
    int i = blockIdx.x * blockDim.x + threadIdx.x;
    if (i < NTOT) g_fill[i] = g_off[i];
}
__global__ void scatter_kernel(const int* __restrict__ src, const int* __restrict__ dst) {
    int e = blockIdx.x * blockDim.x + threadIdx.x;
    if (e >= EDGES) return;
    int p = atomicAdd(&g_fill[dst[e]], 1);
    g_csr[p] = src[e];
}

// ---------------- fp32 GEMM: C[M,N] = A[M,K] @ B[K,N], row-major ----------------
#define GBM 128
#define GBN 64
#define GBK 16
__global__ __launch_bounds__(256) void gemm_kernel(const float* __restrict__ A,
                                                   const float* __restrict__ B,
                                                   float* __restrict__ C,
                                                   int M, int N, int K) {
    __shared__ float As[GBK][GBM+4];
    __shared__ float Bs[GBK][GBN];
    int tid = threadIdx.x;
    int bm = blockIdx.y * GBM;
    int bn = blockIdx.x * GBN;
    int tx = tid & 15, ty = tid >> 4;
    float acc[8][4];
    #pragma unroll
    for (int i = 0; i < 8; i++)
        #pragma unroll
        for (int j = 0; j < 4; j++) acc[i][j] = 0.f;

    for (int k0 = 0; k0 < K; k0 += GBK) {
        // A tile: 128x16
        {
            int c = tid & 15, r0 = tid >> 4;
            #pragma unroll
            for (int i = 0; i < 8; i++) {
                int r = r0 + i*16;
                As[c][r] = A[(bm + r)*K + k0 + c];
            }
        }
        // B tile: 16x64
        {
            int c = tid & 63, r0 = tid >> 6;
            #pragma unroll
            for (int i = 0; i < 4; i++) {
                int r = r0 + i*4;
                Bs[r][c] = B[(k0 + r)*N + bn + c];
            }
        }
        __syncthreads();
        #pragma unroll
        for (int k = 0; k < GBK; k++) {
            float a[8], b[4];
            #pragma unroll
            for (int i = 0; i < 8; i++) a[i] = As[k][ty*8 + i];
            #pragma unroll
            for (int j = 0; j < 4; j++) b[j] = Bs[k][tx*4 + j];
            #pragma unroll
            for (int i = 0; i < 8; i++)
                #pragma unroll
                for (int j = 0; j < 4; j++) acc[i][j] = fmaf(a[i], b[j], acc[i][j]);
        }
        __syncthreads();
    }
    #pragma unroll
    for (int i = 0; i < 8; i++) {
        int row = bm + ty*8 + i;
        #pragma unroll
        for (int j = 0; j < 4; j++)
            C[row*N + bn + tx*4 + j] = acc[i][j];
    }
}

// ---------------- es/ed: per-node per-head dots ----------------
__global__ void esed_kernel(const float* __restrict__ a_src, const float* __restrict__ a_dst) {
    int w = (blockIdx.x * blockDim.x + threadIdx.x) >> 5;
    if (w >= NTOT) return;
    int lane = threadIdx.x & 31;
    int head = lane >> 3;
    int dbase = lane * 8;
    const float4* wh = (const float4*)&g_Wh[w*NHID + dbase];
    const float4* as = (const float4*)&a_src[dbase];
    const float4* ad = (const float4*)&a_dst[dbase];
    float4 w0 = wh[0], w1 = wh[1];
    float4 s0 = as[0], s1 = as[1];
    float4 d0 = ad[0], d1 = ad[1];
    float ps = w0.x*s0.x + w0.y*s0.y + w0.z*s0.z + w0.w*s0.w
             + w1.x*s1.x + w1.y*s1.y + w1.z*s1.z + w1.w*s1.w;
    float pd = w0.x*d0.x + w0.y*d0.y + w0.z*d0.z + w0.w*d0.w
             + w1.x*d1.x + w1.y*d1.y + w1.z*d1.z + w1.w*d1.w;
    #pragma unroll
    for (int o = 4; o; o >>= 1) {
        ps += __shfl_xor_sync(0xffffffffu, ps, o);
        pd += __shfl_xor_sync(0xffffffffu, pd, o);
    }
    if ((lane & 7) == 0) {
        g_es[w*4 + head] = ps;
        g_ed[w*4 + head] = pd;
    }
}

// ---------------- edge kernel: warp per dst node ----------------
__global__ void edge_kernel(int last) {
    int w = (blockIdx.x * blockDim.x + threadIdx.x) >> 5;
    if (w >= NTOT) return;
    int lane = threadIdx.x & 31;
    int beg = g_off[w], end = g_off[w+1];
    float4 edv = *(const float4*)&g_ed[w*4];

    // pass 1: per-head max
    float m0 = -1e30f, m1 = -1e30f, m2 = -1e30f, m3 = -1e30f;
    for (int i = beg + lane; i < end; i += 32) {
        int s = g_csr[i];
        float4 esv = *(const float4*)&g_es[s*4];
        m0 = fmaxf(m0, lrelu(esv.x + edv.x));
        m1 = fmaxf(m1, lrelu(esv.y + edv.y));
        m2 = fmaxf(m2, lrelu(esv.z + edv.z));
        m3 = fmaxf(m3, lrelu(esv.w + edv.w));
    }
    #pragma unroll
    for (int o = 16; o; o >>= 1) {
        m0 = fmaxf(m0, __shfl_xor_sync(0xffffffffu, m0, o));
        m1 = fmaxf(m1, __shfl_xor_sync(0xffffffffu, m1, o));
        m2 = fmaxf(m2, __shfl_xor_sync(0xffffffffu, m2, o));
        m3 = fmaxf(m3, __shfl_xor_sync(0xffffffffu, m3, o));
    }

    // pass 2: denominators
    float d0 = 0.f, d1 = 0.f, d2 = 0.f, d3 = 0.f;
    for (int i = beg + lane; i < end; i += 32) {
        int s = g_csr[i];
        float4 esv = *(const float4*)&g_es[s*4];
        d0 += expf(lrelu(esv.x + edv.x) - m0);
        d1 += expf(lrelu(esv.y + edv.y) - m1);
        d2 += expf(lrelu(esv.z + edv.z) - m2);
        d3 += expf(lrelu(esv.w + edv.w) - m3);
    }
    #pragma unroll
    for (int o = 16; o; o >>= 1) {
        d0 += __shfl_xor_sync(0xffffffffu, d0, o);
        d1 += __shfl_xor_sync(0xffffffffu, d1, o);
        d2 += __shfl_xor_sync(0xffffffffu, d2, o);
        d3 += __shfl_xor_sync(0xffffffffu, d3, o);
    }
    float i0 = 1.f/(d0 + 1e-9f), i1 = 1.f/(d1 + 1e-9f);
    float i2 = 1.f/(d2 + 1e-9f), i3 = 1.f/(d3 + 1e-9f);

    // pass 3: attn + message accumulate
    float acc[8];
    #pragma unroll
    for (int i = 0; i < 8; i++) acc[i] = 0.f;
    int head = lane >> 3;
    float ascore = 0.f;
    for (int s0 = beg; s0 < end; s0 += 32) {
        int i = s0 + lane;
        int src = 0;
        float a0 = 0.f, a1 = 0.f, a2 = 0.f, a3 = 0.f;
        if (i < end) {
            src = g_csr[i];
            float4 esv = *(const float4*)&g_es[src*4];
            a0 = expf(lrelu(esv.x + edv.x) - m0) * i0;
            a1 = expf(lrelu(esv.y + edv.y) - m1) * i1;
            a2 = expf(lrelu(esv.z + edv.z) - m2) * i2;
            a3 = expf(lrelu(esv.w + edv.w) - m3) * i3;
            ascore += 0.25f * (a0 + a1 + a2 + a3);
        }
        int cnt = end - s0; if (cnt > 32) cnt = 32;
        for (int j = 0; j < cnt; j++) {
            int sj = __shfl_sync(0xffffffffu, src, j);
            float b0 = __shfl_sync(0xffffffffu, a0, j);
            float b1 = __shfl_sync(0xffffffffu, a1, j);
            float b2 = __shfl_sync(0xffffffffu, a2, j);
            float b3 = __shfl_sync(0xffffffffu, a3, j);
            float aj = (head == 0) ? b0 : (head == 1) ? b1 : (head == 2) ? b2 : b3;
            const float4* wp = (const float4*)&g_Wh[sj*NHID + lane*8];
            float4 w0 = wp[0], w1 = wp[1];
            acc[0] = fmaf(aj, w0.x, acc[0]); acc[1] = fmaf(aj, w0.y, acc[1]);
            acc[2] = fmaf(aj, w0.z, acc[2]); acc[3] = fmaf(aj, w0.w, acc[3]);
            acc[4] = fmaf(aj, w1.x, acc[4]); acc[5] = fmaf(aj, w1.y, acc[5]);
            acc[6] = fmaf(aj, w1.z, acc[6]); acc[7] = fmaf(aj, w1.w, acc[7]);
        }
    }
    float4* mp = (float4*)&g_msg[w*NHID + lane*8];
    mp[0] = make_float4(acc[0], acc[1], acc[2], acc[3]);
    mp[1] = make_float4(acc[4], acc[5], acc[6], acc[7]);

    if (last) {
        #pragma unroll
        for (int o = 16; o; o >>= 1) ascore += __shfl_xor_sync(0xffffffffu, ascore, o);
        if (lane == 0) g_ascore[w] = ascore;
    }
}

// ---------------- gates: z, r*h ----------------
__global__ void gate_kernel(const float* __restrict__ bz, const float* __restrict__ br) {
    int idx = blockIdx.x * blockDim.x + threadIdx.x;
    if (idx >= NTOT*NHID) return;
    int v = idx >> 8, d = idx & 255;
    float mz = g_gm[v*768 + d],        mr = g_gm[v*768 + 256 + d];
    float hz = g_gh[v*512 + d],        hr = g_gh[v*512 + 256 + d];
    float z = 1.f / (1.f + expf(-(mz + hz + bz[d])));
    float r = 1.f / (1.f + expf(-(mr + hr + br[d])));
    g_z[idx]  = z;
    g_rh[idx] = r * g_h[idx];
}

// ---------------- GRU update (masked by turn) ----------------
__global__ void update_kernel(const float* __restrict__ bn, const int* __restrict__ tid_arr, int t) {
    int idx = blockIdx.x * blockDim.x + threadIdx.x;
    if (idx >= NTOT*NHID) return;
    int v = idx >> 8, d = idx & 255;
    float n = tanhf(g_gm[v*768 + 512 + d] + g_rn[idx] + bn[d]);
    float z = g_z[idx];
    float h = g_h[idx];
    float hn = (1.f - z) * h + z * n;
    g_h[idx] = (tid_arr[v] == t) ? hn : h;
}

// ---------------- pooling: per-(b,t) softmax-weighted mean ----------------
__global__ void pool_kernel() {  // grid = 96, block = 256
    __shared__ float sa[128];
    __shared__ float sred[256];
    int bt = blockIdx.x;
    int base = bt * NN;
    int tid = threadIdx.x;
    float sc = (tid < 128) ? g_ascore[base + tid] : -1e30f;
    sred[tid] = sc; __syncthreads();
    for (int s = 128; s > 0; s >>= 1) {
        if (tid < s) sred[tid] = fmaxf(sred[tid], sred[tid + s]);
        __syncthreads();
    }
    float mx = sred[0]; __syncthreads();
    float e = (tid < 128) ? expf(sc - mx) : 0.f;
    sred[tid] = e; __syncthreads();
    for (int s = 128; s > 0; s >>= 1) {
        if (tid < s) sred[tid] += sred[tid + s];
        __syncthreads();
    }
    float tot = sred[0];
    if (tid < 128) sa[tid] = e / tot;
    __syncthreads();
    float acc = 0.f;
    for (int n = 0; n < NN; n++)
        acc = fmaf(g_h[(base + n)*NHID + tid], sa[n], acc);
    g_pooled[bt*NHID + tid] = acc * (1.f/128.f);
}

// ---------------- output: r1 = even turns, r2 = odd turns ----------------
__global__ void out_kernel(float* __restrict__ out) {
    int i = blockIdx.x * blockDim.x + threadIdx.x;
    if (i >= BB*NHID) return;
    int b = i >> 8, d = i & 255;
    float r1 = g_pooled[(b*TT + 0)*NHID + d] + g_pooled[(b*TT + 2)*NHID + d] + g_pooled[(b*TT + 4)*NHID + d];
    float r2 = g_pooled[(b*TT + 1)*NHID + d] + g_pooled[(b*TT + 3)*NHID + d] + g_pooled[(b*TT + 5)*NHID + d];
    out[b*NHID + d] = r1;
    out[BB*NHID + b*NHID + d] = r2;
}

// ---------------- host ----------------
extern "C" void kernel_launch(void* const* d_in, const int* in_sizes, int n_in,
                              void* d_out, int out_size) {
    const float* emb    = (const float*)d_in[0];
    const float* nmask  = (const float*)d_in[1];
    const float* W      = (const float*)d_in[2];
    const float* a_src  = (const float*)d_in[3];
    const float* a_dst  = (const float*)d_in[4];
    const float* Wz     = (const float*)d_in[5];
    const float* Uz     = (const float*)d_in[6];
    const float* Wr     = (const float*)d_in[7];
    const float* Ur     = (const float*)d_in[8];
    const float* Wn     = (const float*)d_in[9];
    const float* Un     = (const float*)d_in[10];
    const float* bz     = (const float*)d_in[11];
    const float* br     = (const float*)d_in[12];
    const float* bn     = (const float*)d_in[13];
    const int*   nodeidx= (const int*)d_in[14];
    const int*   esrc   = (const int*)d_in[15];
    const int*   edst   = (const int*)d_in[16];
    const int*   tidarr = (const int*)d_in[17];
    float* out = (float*)d_out;

    float *p_h, *p_Wh, *p_msg, *p_gm, *p_gh, *p_rh, *p_rn, *p_Wcat, *p_Ucat;
    cudaGetSymbolAddress((void**)&p_h,    g_h);
    cudaGetSymbolAddress((void**)&p_Wh,   g_Wh);
    cudaGetSymbolAddress((void**)&p_msg,  g_msg);
    cudaGetSymbolAddress((void**)&p_gm,   g_gm);
    cudaGetSymbolAddress((void**)&p_gh,   g_gh);
    cudaGetSymbolAddress((void**)&p_rh,   g_rh);
    cudaGetSymbolAddress((void**)&p_rn,   g_rn);
    cudaGetSymbolAddress((void**)&p_Wcat, g_Wcat);
    cudaGetSymbolAddress((void**)&p_Ucat, g_Ucat);

    // prep
    concat_kernel<<<256, 256>>>(Wz, Uz, Wr, Ur, Wn);
    init_kernel<<<(NTOT*NHID)/256, 256>>>(emb, nmask, nodeidx);
    zero_cnt_kernel<<<48, 256>>>();
    count_kernel<<<EDGES/256, 256>>>(edst);
    scan_kernel<<<1, 1024>>>();
    fill_kernel<<<48, 256>>>();
    scatter_kernel<<<EDGES/256, 256>>>(esrc, edst);

    const int warpBlocks = (NTOT*32)/256;  // 1536

    for (int t = 0; t < TT; t++) {
        // Wh = h @ W
        gemm_kernel<<<dim3(256/GBN, NTOT/GBM), 256>>>(p_h, W, p_Wh, NTOT, 256, 256);
        esed_kernel<<<warpBlocks, 256>>>(a_src, a_dst);
        edge_kernel<<<warpBlocks, 256>>>((t == TT-1) ? 1 : 0);
        // gm = msg @ [Wz|Wr|Wn],  gh = h @ [Uz|Ur]
        gemm_kernel<<<dim3(768/GBN, NTOT/GBM), 256>>>(p_msg, p_Wcat, p_gm, NTOT, 768, 256);
        gemm_kernel<<<dim3(512/GBN, NTOT/GBM), 256>>>(p_h,   p_Ucat, p_gh, NTOT, 512, 256);
        gate_kernel<<<(NTOT*NHID)/256, 256>>>(bz, br);
        // rn = (r*h) @ Un
        gemm_kernel<<<dim3(256/GBN, NTOT/GBM), 256>>>(p_rh, Un, p_rn, NTOT, 256, 256);
        update_kernel<<<(NTOT*NHID)/256, 256>>>(bn, tidarr, t);
    }

    pool_kernel<<<BB*TT, 256>>>();
    out_kernel<<<BB*NHID/256, 256>>>(out);
    (void)in_sizes; (void)n_in; (void)out_size;
}

// round 2
// speedup vs baseline: 2.7490x; 2.7490x over previous
#include <cuda_runtime.h>
#include <cuda_bf16.h>
#include <math.h>

// ---------------- problem constants ----------------
#define NFEAT 256
#define NHID  256
#define NHEADS 4
#define DH 64
#define ALPHA 0.2f
#define BB 16
#define TT 6
#define NN 128
#define NTOT (BB*TT*NN)      // 12288
#define DEG 16
#define EDGES (NTOT*DEG)     // 196608
#define NSEL (BB*NN)         // 2048 nodes per turn

// ---------------- scratch (device globals) ----------------
__device__ float g_h[NTOT*NHID];
__device__ float g_Wh[NTOT*NHID];
__device__ float g_msg[NTOT*NHID];
__device__ float g_es[NTOT*4];
__device__ float g_ed[NTOT*4];
__device__ float g_gm[NTOT*768];
__device__ float g_gh[NTOT*512];
__device__ float g_z[NTOT*NHID];
__device__ float g_rh[NTOT*NHID];
__device__ float g_rn[NTOT*NHID];
__device__ float g_Wcat[256*768];
__device__ float g_Ucat[256*512];
__device__ int   g_cnt[NTOT];
__device__ int   g_off[NTOT+1];
__device__ int   g_fill[NTOT];
__device__ int   g_csr[EDGES];
__device__ float g_ascore[NTOT];
__device__ float g_pooled[BB*TT*NHID];

__device__ __forceinline__ float lrelu(float x){ return x >= 0.f ? x : ALPHA * x; }

// ---------------- weight concat ----------------
__global__ void concat_kernel(const float* __restrict__ Wz, const float* __restrict__ Uz,
                              const float* __restrict__ Wr, const float* __restrict__ Ur,
                              const float* __restrict__ Wn) {
    int i = blockIdx.x * blockDim.x + threadIdx.x;
    if (i >= 256*256) return;
    int k = i >> 8, j = i & 255;
    g_Wcat[k*768 + j]       = Wz[i];
    g_Wcat[k*768 + 256 + j] = Wr[i];
    g_Wcat[k*768 + 512 + j] = Wn[i];
    g_Ucat[k*512 + j]       = Uz[i];
    g_Ucat[k*512 + 256 + j] = Ur[i];
}

// ---------------- h init ----------------
__global__ void init_kernel(const float* __restrict__ emb, const float* __restrict__ nmask,
                            const int* __restrict__ nodeidx) {
    int idx = blockIdx.x * blockDim.x + threadIdx.x;
    if (idx >= NTOT*NHID) return;
    int v = idx >> 8, d = idx & 255;
    int s = nodeidx[v];
    g_h[idx] = emb[s*NFEAT + d] * nmask[s];
}

// ---------------- CSR build ----------------
__global__ void zero_cnt_kernel() {
    int i = blockIdx.x * blockDim.x + threadIdx.x;
    if (i < NTOT) g_cnt[i] = 0;
}
__global__ void count_kernel(const int* __restrict__ dst) {
    int e = blockIdx.x * blockDim.x + threadIdx.x;
    if (e < EDGES) atomicAdd(&g_cnt[dst[e]], 1);
}
__global__ void scan_kernel() {
    __shared__ int s[1024];
    __shared__ int carry;
    int tid = threadIdx.x;
    if (tid == 0) { carry = 0; g_off[0] = 0; }
    __syncthreads();
    for (int c = 0; c < NTOT/1024; c++) {
        int i = c*1024 + tid;
        s[tid] = g_cnt[i];
        __syncthreads();
        for (int d = 1; d < 1024; d <<= 1) {
            int t = (tid >= d) ? s[tid-d] : 0;
            __syncthreads();
            s[tid] += t;
            __syncthreads();
        }
        g_off[i+1] = carry + s[tid];
        __syncthreads();
        if (tid == 0) carry += s[1023];
        __syncthreads();
    }
}
__global__ void fill_kernel() {
    int i = blockIdx.x * blockDim.x + threadIdx.x;
    if (i < NTOT) g_fill[i] = g_off[i];
}
__global__ void scatter_kernel(const int* __restrict__ src, const int* __restrict__ dst) {
    int e = blockIdx.x * blockDim.x + threadIdx.x;
    if (e >= EDGES) return;
    int p = atomicAdd(&g_fill[dst[e]], 1);
    g_csr[p] = src[e];
}

// ---------------- double-buffered fp32 GEMM body ----------------
template<int BM, int BN, int TM, int TN>
__device__ __forceinline__ void gemm_body(const float* __restrict__ A, const float* __restrict__ B,
                                          float* __restrict__ C, int N, int K,
                                          int row0, int col0) {
    constexpr int BK = 16;
    constexpr int NT = (BM/TM)*(BN/TN);
    constexpr int AIT = (BM*BK/4)/NT;
    constexpr int BIT = (BK*BN/4)/NT;
    __shared__ float As[2][BK][BM+4];
    __shared__ float Bs[2][BK][BN];
    int tid = threadIdx.x;
    int tx = tid % (BN/TN), ty = tid / (BN/TN);
    float acc[TM][TN];
    #pragma unroll
    for (int i = 0; i < TM; i++)
        #pragma unroll
        for (int j = 0; j < TN; j++) acc[i][j] = 0.f;
    float4 aReg[AIT], bReg[BIT];

    // prologue: slab 0
    #pragma unroll
    for (int i = 0; i < AIT; i++) {
        int f = tid + i*NT; int r = f >> 2, c = (f & 3)*4;
        aReg[i] = *(const float4*)&A[(row0 + r)*K + c];
    }
    #pragma unroll
    for (int i = 0; i < BIT; i++) {
        int f = tid + i*NT; int r = f / (BN/4), c = (f % (BN/4))*4;
        bReg[i] = *(const float4*)&B[r*N + col0 + c];
    }
    #pragma unroll
    for (int i = 0; i < AIT; i++) {
        int f = tid + i*NT; int r = f >> 2, c = (f & 3)*4;
        As[0][c+0][r] = aReg[i].x; As[0][c+1][r] = aReg[i].y;
        As[0][c+2][r] = aReg[i].z; As[0][c+3][r] = aReg[i].w;
    }
    #pragma unroll
    for (int i = 0; i < BIT; i++) {
        int f = tid + i*NT; int r = f / (BN/4), c = (f % (BN/4))*4;
        *(float4*)&Bs[0][r][c] = bReg[i];
    }
    __syncthreads();

    int nSlab = K / BK;
    for (int s = 0; s < nSlab; s++) {
        if (s+1 < nSlab) {
            int k0 = (s+1)*BK;
            #pragma unroll
            for (int i = 0; i < AIT; i++) {
                int f = tid + i*NT; int r = f >> 2, c = (f & 3)*4;
                aReg[i] = *(const float4*)&A[(row0 + r)*K + k0 + c];
            }
            #pragma unroll
            for (int i = 0; i < BIT; i++) {
                int f = tid + i*NT; int r = f / (BN/4), c = (f % (BN/4))*4;
                bReg[i] = *(const float4*)&B[(k0 + r)*N + col0 + c];
            }
        }
        int buf = s & 1;
        #pragma unroll
        for (int k = 0; k < BK; k++) {
            float a[TM], b[TN];
            #pragma unroll
            for (int i = 0; i < TM/4; i++) {
                float4 v = *(const float4*)&As[buf][k][ty*TM + i*4];
                a[i*4+0]=v.x; a[i*4+1]=v.y; a[i*4+2]=v.z; a[i*4+3]=v.w;
            }
            #pragma unroll
            for (int j = 0; j < TN/4; j++) {
                float4 v = *(const float4*)&Bs[buf][k][tx*TN + j*4];
                b[j*4+0]=v.x; b[j*4+1]=v.y; b[j*4+2]=v.z; b[j*4+3]=v.w;
            }
            #pragma unroll
            for (int i = 0; i < TM; i++)
                #pragma unroll
                for (int j = 0; j < TN; j++) acc[i][j] = fmaf(a[i], b[j], acc[i][j]);
        }
        if (s+1 < nSlab) {
            int nb = buf ^ 1;
            #pragma unroll
            for (int i = 0; i < AIT; i++) {
                int f = tid + i*NT; int r = f >> 2, c = (f & 3)*4;
                As[nb][c+0][r] = aReg[i].x; As[nb][c+1][r] = aReg[i].y;
                As[nb][c+2][r] = aReg[i].z; As[nb][c+3][r] = aReg[i].w;
            }
            #pragma unroll
            for (int i = 0; i < BIT; i++) {
                int f = tid + i*NT; int r = f / (BN/4), c = (f % (BN/4))*4;
                *(float4*)&Bs[nb][r][c] = bReg[i];
            }
        }
        __syncthreads();
    }

    #pragma unroll
    for (int i = 0; i < TM; i++) {
        int r = row0 + ty*TM + i;
        #pragma unroll
        for (int j = 0; j < TN; j += 4) {
            float4 v = make_float4(acc[i][j], acc[i][j+1], acc[i][j+2], acc[i][j+3]);
            *(float4*)&C[r*N + col0 + tx*TN + j] = v;
        }
    }
}

__global__ __launch_bounds__(256) void gemm128x128(const float* __restrict__ A, const float* __restrict__ B,
                                                   float* __restrict__ C, int N, int K,
                                                   int rowStride, int rowOff) {
    gemm_body<128,128,8,8>(A, B, C, N, K, blockIdx.y*rowStride + rowOff, blockIdx.x*128);
}
__global__ __launch_bounds__(256) void gemm128x64(const float* __restrict__ A, const float* __restrict__ B,
                                                  float* __restrict__ C, int N, int K,
                                                  int rowStride, int rowOff) {
    gemm_body<128,64,8,4>(A, B, C, N, K, blockIdx.y*rowStride + rowOff, blockIdx.x*64);
}
// fused gm = msg@Wcat (N=768) and gh = h@Ucat (N=512) on turn-t rows
__global__ __launch_bounds__(256) void gemm_gates(const float* __restrict__ msg, const float* __restrict__ Wcat,
                                                  float* __restrict__ gm, const float* __restrict__ h,
                                                  const float* __restrict__ Ucat, float* __restrict__ gh,
                                                  int t) {
    int row0 = blockIdx.y*768 + t*128;
    const float* A; const float* Bm; float* C; int N;
    if (blockIdx.z == 0) { A = msg; Bm = Wcat; C = gm; N = 768; }
    else { if (blockIdx.x >= 4) return; A = h; Bm = Ucat; C = gh; N = 512; }
    gemm_body<128,128,8,8>(A, Bm, C, N, 256, row0, blockIdx.x*128);
}

// ---------------- es/ed dots (remappable row set) ----------------
__global__ void esed_kernel(const float* __restrict__ a_src, const float* __restrict__ a_dst,
                            int nW, int stride, int off) {
    int w = (blockIdx.x * blockDim.x + threadIdx.x) >> 5;
    if (w >= nW) return;
    int node = (w >> 7)*stride + off + (w & 127);
    int lane = threadIdx.x & 31;
    int head = lane >> 3;
    int dbase = lane * 8;
    const float4* wh = (const float4*)&g_Wh[node*NHID + dbase];
    const float4* as = (const float4*)&a_src[dbase];
    const float4* ad = (const float4*)&a_dst[dbase];
    float4 w0 = wh[0], w1 = wh[1];
    float4 s0 = as[0], s1 = as[1];
    float4 d0 = ad[0], d1 = ad[1];
    float ps = w0.x*s0.x + w0.y*s0.y + w0.z*s0.z + w0.w*s0.w
             + w1.x*s1.x + w1.y*s1.y + w1.z*s1.z + w1.w*s1.w;
    float pd = w0.x*d0.x + w0.y*d0.y + w0.z*d0.z + w0.w*d0.w
             + w1.x*d1.x + w1.y*d1.y + w1.z*d1.z + w1.w*d1.w;
    #pragma unroll
    for (int o = 4; o; o >>= 1) {
        ps += __shfl_xor_sync(0xffffffffu, ps, o);
        pd += __shfl_xor_sync(0xffffffffu, pd, o);
    }
    if ((lane & 7) == 0) {
        g_es[node*4 + head] = ps;
        g_ed[node*4 + head] = pd;
    }
}

// ---------------- edge kernel: warp per dst node ----------------
__global__ void edge_kernel(int nW, int stride, int off, int last) {
    int w = (blockIdx.x * blockDim.x + threadIdx.x) >> 5;
    if (w >= nW) return;
    int lane = threadIdx.x & 31;
    int node = last ? w : (w >> 7)*stride + off + (w & 127);
    int doMsg = last ? (((w >> 7) % TT) == TT-1) : 1;
    int beg = g_off[node], end = g_off[node+1];
    float4 edv = *(const float4*)&g_ed[node*4];

    // pass 1: per-head max
    float m0 = -1e30f, m1 = -1e30f, m2 = -1e30f, m3 = -1e30f;
    for (int i = beg + lane; i < end; i += 32) {
        int s = g_csr[i];
        float4 esv = *(const float4*)&g_es[s*4];
        m0 = fmaxf(m0, lrelu(esv.x + edv.x));
        m1 = fmaxf(m1, lrelu(esv.y + edv.y));
        m2 = fmaxf(m2, lrelu(esv.z + edv.z));
        m3 = fmaxf(m3, lrelu(esv.w + edv.w));
    }
    #pragma unroll
    for (int o = 16; o; o >>= 1) {
        m0 = fmaxf(m0, __shfl_xor_sync(0xffffffffu, m0, o));
        m1 = fmaxf(m1, __shfl_xor_sync(0xffffffffu, m1, o));
        m2 = fmaxf(m2, __shfl_xor_sync(0xffffffffu, m2, o));
        m3 = fmaxf(m3, __shfl_xor_sync(0xffffffffu, m3, o));
    }

    // pass 2: denominators
    float d0 = 0.f, d1 = 0.f, d2 = 0.f, d3 = 0.f;
    for (int i = beg + lane; i < end; i += 32) {
        int s = g_csr[i];
        float4 esv = *(const float4*)&g_es[s*4];
        d0 += expf(lrelu(esv.x + edv.x) - m0);
        d1 += expf(lrelu(esv.y + edv.y) - m1);
        d2 += expf(lrelu(esv.z + edv.z) - m2);
        d3 += expf(lrelu(esv.w + edv.w) - m3);
    }
    #pragma unroll
    for (int o = 16; o; o >>= 1) {
        d0 += __shfl_xor_sync(0xffffffffu, d0, o);
        d1 += __shfl_xor_sync(0xffffffffu, d1, o);
        d2 += __shfl_xor_sync(0xffffffffu, d2, o);
        d3 += __shfl_xor_sync(0xffffffffu, d3, o);
    }
    float i0 = 1.f/(d0 + 1e-9f), i1 = 1.f/(d1 + 1e-9f);
    float i2 = 1.f/(d2 + 1e-9f), i3 = 1.f/(d3 + 1e-9f);

    if (last && lane == 0)
        g_ascore[node] = 0.25f * (d0*i0 + d1*i1 + d2*i2 + d3*i3);

    if (!doMsg) return;

    // pass 3: attn + message accumulate
    float acc[8];
    #pragma unroll
    for (int i = 0; i < 8; i++) acc[i] = 0.f;
    int head = lane >> 3;
    for (int s0 = beg; s0 < end; s0 += 32) {
        int i = s0 + lane;
        int src = 0;
        float a0 = 0.f, a1 = 0.f, a2 = 0.f, a3 = 0.f;
        if (i < end) {
            src = g_csr[i];
            float4 esv = *(const float4*)&g_es[src*4];
            a0 = expf(lrelu(esv.x + edv.x) - m0) * i0;
            a1 = expf(lrelu(esv.y + edv.y) - m1) * i1;
            a2 = expf(lrelu(esv.z + edv.z) - m2) * i2;
            a3 = expf(lrelu(esv.w + edv.w) - m3) * i3;
        }
        int cnt = end - s0; if (cnt > 32) cnt = 32;
        for (int j = 0; j < cnt; j++) {
            int sj = __shfl_sync(0xffffffffu, src, j);
            float b0 = __shfl_sync(0xffffffffu, a0, j);
            float b1 = __shfl_sync(0xffffffffu, a1, j);
            float b2 = __shfl_sync(0xffffffffu, a2, j);
            float b3 = __shfl_sync(0xffffffffu, a3, j);
            float aj = (head == 0) ? b0 : (head == 1) ? b1 : (head == 2) ? b2 : b3;
            const float4* wp = (const float4*)&g_Wh[sj*NHID + lane*8];
            float4 w0 = wp[0], w1 = wp[1];
            acc[0] = fmaf(aj, w0.x, acc[0]); acc[1] = fmaf(aj, w0.y, acc[1]);
            acc[2] = fmaf(aj, w0.z, acc[2]); acc[3] = fmaf(aj, w0.w, acc[3]);
            acc[4] = fmaf(aj, w1.x, acc[4]); acc[5] = fmaf(aj, w1.y, acc[5]);
            acc[6] = fmaf(aj, w1.z, acc[6]); acc[7] = fmaf(aj, w1.w, acc[7]);
        }
    }
    float4* mp = (float4*)&g_msg[node*NHID + lane*8];
    mp[0] = make_float4(acc[0], acc[1], acc[2], acc[3]);
    mp[1] = make_float4(acc[4], acc[5], acc[6], acc[7]);
}

// ---------------- gates on turn-t rows ----------------
__global__ void gate_kernel(const float* __restrict__ bz, const float* __restrict__ br, int t) {
    int idx = blockIdx.x * blockDim.x + threadIdx.x;
    if (idx >= NSEL*NHID) return;
    int vl = idx >> 8, d = idx & 255;
    int v = (vl >> 7)*768 + t*128 + (vl & 127);
    float mz = g_gm[v*768 + d],       mr = g_gm[v*768 + 256 + d];
    float hz = g_gh[v*512 + d],       hr = g_gh[v*512 + 256 + d];
    float z = 1.f / (1.f + expf(-(mz + hz + bz[d])));
    float r = 1.f / (1.f + expf(-(mr + hr + br[d])));
    g_z[v*256 + d]  = z;
    g_rh[v*256 + d] = r * g_h[v*256 + d];
}

// ---------------- GRU update on turn-t rows ----------------
__global__ void update_kernel(const float* __restrict__ bn, int t) {
    int idx = blockIdx.x * blockDim.x + threadIdx.x;
    if (idx >= NSEL*NHID) return;
    int vl = idx >> 8, d = idx & 255;
    int v = (vl >> 7)*768 + t*128 + (vl & 127);
    float n = tanhf(g_gm[v*768 + 512 + d] + g_rn[v*256 + d] + bn[d]);
    float z = g_z[v*256 + d];
    float h = g_h[v*256 + d];
    g_h[v*256 + d] = (1.f - z) * h + z * n;
}

// ---------------- pooling ----------------
__global__ void pool_kernel() {
    __shared__ float sa[128];
    __shared__ float sred[256];
    int bt = blockIdx.x;
    int base = bt * NN;
    int tid = threadIdx.x;
    float sc = (tid < 128) ? g_ascore[base + tid] : -1e30f;
    sred[tid] = sc; __syncthreads();
    for (int s = 128; s > 0; s >>= 1) {
        if (tid < s) sred[tid] = fmaxf(sred[tid], sred[tid + s]);
        __syncthreads();
    }
    float mx = sred[0]; __syncthreads();
    float e = (tid < 128) ? expf(sc - mx) : 0.f;
    sred[tid] = e; __syncthreads();
    for (int s = 128; s > 0; s >>= 1) {
        if (tid < s) sred[tid] += sred[tid + s];
        __syncthreads();
    }
    float tot = sred[0];
    if (tid < 128) sa[tid] = e / tot;
    __syncthreads();
    float acc = 0.f;
    for (int n = 0; n < NN; n++)
        acc = fmaf(g_h[(base + n)*NHID + tid], sa[n], acc);
    g_pooled[bt*NHID + tid] = acc * (1.f/128.f);
}

__global__ void out_kernel(float* __restrict__ out) {
    int i = blockIdx.x * blockDim.x + threadIdx.x;
    if (i >= BB*NHID) return;
    int b = i >> 8, d = i & 255;
    float r1 = g_pooled[(b*TT + 0)*NHID + d] + g_pooled[(b*TT + 2)*NHID + d] + g_pooled[(b*TT + 4)*NHID + d];
    float r2 = g_pooled[(b*TT + 1)*NHID + d] + g_pooled[(b*TT + 3)*NHID + d] + g_pooled[(b*TT + 5)*NHID + d];
    out[b*NHID + d] = r1;
    out[BB*NHID + b*NHID + d] = r2;
}

// ---------------- host ----------------
extern "C" void kernel_launch(void* const* d_in, const int* in_sizes, int n_in,
                              void* d_out, int out_size) {
    const float* emb    = (const float*)d_in[0];
    const float* nmask  = (const float*)d_in[1];
    const float* W      = (const float*)d_in[2];
    const float* a_src  = (const float*)d_in[3];
    const float* a_dst  = (const float*)d_in[4];
    const float* Wz     = (const float*)d_in[5];
    const float* Uz     = (const float*)d_in[6];
    const float* Wr     = (const float*)d_in[7];
    const float* Ur     = (const float*)d_in[8];
    const float* Wn     = (const float*)d_in[9];
    const float* Un     = (const float*)d_in[10];
    const float* bz     = (const float*)d_in[11];
    const float* br     = (const float*)d_in[12];
    const float* bn     = (const float*)d_in[13];
    const int*   nodeidx= (const int*)d_in[14];
    const int*   esrc   = (const int*)d_in[15];
    const int*   edst   = (const int*)d_in[16];
    float* out = (float*)d_out;

    float *p_h, *p_Wh, *p_msg, *p_gm, *p_gh, *p_rh, *p_rn, *p_Wcat, *p_Ucat;
    cudaGetSymbolAddress((void**)&p_h,    g_h);
    cudaGetSymbolAddress((void**)&p_Wh,   g_Wh);
    cudaGetSymbolAddress((void**)&p_msg,  g_msg);
    cudaGetSymbolAddress((void**)&p_gm,   g_gm);
    cudaGetSymbolAddress((void**)&p_gh,   g_gh);
    cudaGetSymbolAddress((void**)&p_rh,   g_rh);
    cudaGetSymbolAddress((void**)&p_rn,   g_rn);
    cudaGetSymbolAddress((void**)&p_Wcat, g_Wcat);
    cudaGetSymbolAddress((void**)&p_Ucat, g_Ucat);

    // prep
    concat_kernel<<<256, 256>>>(Wz, Uz, Wr, Ur, Wn);
    init_kernel<<<(NTOT*NHID)/256, 256>>>(emb, nmask, nodeidx);
    zero_cnt_kernel<<<48, 256>>>();
    count_kernel<<<EDGES/256, 256>>>(edst);
    scan_kernel<<<1, 1024>>>();
    fill_kernel<<<48, 256>>>();
    scatter_kernel<<<EDGES/256, 256>>>(esrc, edst);

    const int fullWarpBlocks = (NTOT*32)/256;   // 1536
    const int selWarpBlocks  = (NSEL*32)/256;   // 256

    for (int t = 0; t < TT; t++) {
        if (t == 0) {
            // full Wh = h @ W
            gemm128x128<<<dim3(2, NTOT/128), 256>>>(p_h, W, p_Wh, 256, 256, 128, 0);
            esed_kernel<<<fullWarpBlocks, 256>>>(a_src, a_dst, NTOT, 128, 0);
        } else {
            // refresh Wh / es / ed rows of turn t-1 (the only h rows that changed)
            gemm128x128<<<dim3(2, BB), 256>>>(p_h, W, p_Wh, 256, 256, 768, (t-1)*128);
            esed_kernel<<<selWarpBlocks, 256>>>(a_src, a_dst, NSEL, 768, (t-1)*128);
        }
        if (t == TT-1) {
            // all nodes: softmax denominators -> ascore; messages only for turn-5 dsts
            edge_kernel<<<fullWarpBlocks, 256>>>(NTOT, 128, 0, 1);
        } else {
            edge_kernel<<<selWarpBlocks, 256>>>(NSEL, 768, t*128, 0);
        }
        // gm = msg@[Wz|Wr|Wn], gh = h@[Uz|Ur]  (turn-t rows only)
        gemm_gates<<<dim3(6, BB, 2), 256>>>(p_msg, p_Wcat, p_gm, p_h, p_Ucat, p_gh, t);
        gate_kernel<<<(NSEL*NHID)/256, 256>>>(bz, br, t);
        // rn = (r*h) @ Un  (turn-t rows)
        gemm128x64<<<dim3(4, BB), 256>>>(p_rh, Un, p_rn, 256, 256, 768, t*128);
        update_kernel<<<(NSEL*NHID)/256, 256>>>(bn, t);
    }

    pool_kernel<<<BB*TT, 256>>>();
    out_kernel<<<BB*NHID/256, 256>>>(out);
    (void)in_sizes; (void)n_in; (void)out_size;
}

// round 4
// speedup vs baseline: 4.1641x; 1.5148x over previous
#include <cuda_runtime.h>
#include <cuda_bf16.h>
#include <math.h>
#include <stdint.h>

// ---------------- problem constants ----------------
#define NFEAT 256
#define NHID  256
#define NHEADS 4
#define DH 64
#define ALPHA 0.2f
#define BB 16
#define TT 6
#define NN 128
#define NTOT (BB*TT*NN)      // 12288
#define DEG 16
#define EDGES (NTOT*DEG)     // 196608
#define NSEL (BB*NN)         // 2048

// ---------------- scratch (device globals) ----------------
__device__ __align__(16) float g_h[NTOT*NHID];
__device__ __align__(16) float g_Wh[NTOT*NHID];
__device__ __align__(16) float g_gm[NTOT*768];
__device__ __align__(16) float g_gh[NTOT*512];
__device__ __align__(16) float g_z[NTOT*NHID];
__device__ __align__(16) float g_rn[NTOT*NHID];
__device__ __align__(16) float g_es[NTOT*4];
__device__ __align__(16) float g_ed[NTOT*4];
__device__ int   g_cnt[NTOT];
__device__ int   g_off[NTOT+1];
__device__ int   g_fill[NTOT];
__device__ int   g_csr[EDGES];
__device__ float g_ascore[NTOT];
__device__ float g_pooled[BB*TT*NHID];

// bf16 split buffers (hi/lo), activations
__device__ __align__(16) __nv_bfloat16 g_h_hi[NTOT*NHID];
__device__ __align__(16) __nv_bfloat16 g_h_lo[NTOT*NHID];
__device__ __align__(16) __nv_bfloat16 g_msg_hi[NTOT*NHID];
__device__ __align__(16) __nv_bfloat16 g_msg_lo[NTOT*NHID];
__device__ __align__(16) __nv_bfloat16 g_rh_hi[NTOT*NHID];
__device__ __align__(16) __nv_bfloat16 g_rh_lo[NTOT*NHID];
// weights transposed to [N,K] K-major, split
__device__ __align__(16) __nv_bfloat16 g_WT_hi[256*256];
__device__ __align__(16) __nv_bfloat16 g_WT_lo[256*256];
__device__ __align__(16) __nv_bfloat16 g_WcatT_hi[768*256];
__device__ __align__(16) __nv_bfloat16 g_WcatT_lo[768*256];
__device__ __align__(16) __nv_bfloat16 g_UcatT_hi[512*256];
__device__ __align__(16) __nv_bfloat16 g_UcatT_lo[512*256];
__device__ __align__(16) __nv_bfloat16 g_UnT_hi[256*256];
__device__ __align__(16) __nv_bfloat16 g_UnT_lo[256*256];

__device__ __forceinline__ float lrelu(float x){ return x >= 0.f ? x : ALPHA * x; }
__device__ __forceinline__ void bsplit(float v, __nv_bfloat16* hp, __nv_bfloat16* lp){
    __nv_bfloat16 h = __float2bfloat16(v);
    *hp = h;
    *lp = __float2bfloat16(v - __bfloat162float(h));
}

// mma.sync m16n8k16 bf16 (baseline PTX, works on compute_103 target)
#define MMA16816(c, a0,a1,a2,a3, b0,b1) \
    asm volatile("mma.sync.aligned.m16n8k16.row.col.f32.bf16.bf16.f32 " \
        "{%0,%1,%2,%3}, {%4,%5,%6,%7}, {%8,%9}, {%0,%1,%2,%3};" \
        : "+f"((c)[0]), "+f"((c)[1]), "+f"((c)[2]), "+f"((c)[3]) \
        : "r"(a0), "r"(a1), "r"(a2), "r"(a3), "r"(b0), "r"(b1))

// ---------------- HMMA bf16x3 GEMM: C[M,N] = A[M,256] @ B[N,256]^T ----------------
// A row-major hi/lo bf16; B row-major [N,K] (K contiguous) hi/lo bf16; C fp32 row-major.
// Block 256 thr = 8 warps (4m x 2n), BM=BN=128, K=256 in 8 slabs of 32.
__global__ __launch_bounds__(256) void mma_gemm(
    const __nv_bfloat16* __restrict__ Ahi, const __nv_bfloat16* __restrict__ Alo,
    const __nv_bfloat16* __restrict__ Bhi, const __nv_bfloat16* __restrict__ Blo,
    float* __restrict__ C, int N, int rowStride, int rowOff)
{
    __shared__ __nv_bfloat16 sAh[128][40];
    __shared__ __nv_bfloat16 sAl[128][40];
    __shared__ __nv_bfloat16 sBh[128][40];
    __shared__ __nv_bfloat16 sBl[128][40];

    int tid = threadIdx.x;
    int wid = tid >> 5, lane = tid & 31;
    int g = lane >> 2, tig = lane & 3;
    int wm = (wid & 3) * 32;
    int wn = (wid >> 2) * 64;
    int row0 = blockIdx.y * rowStride + rowOff;
    int col0 = blockIdx.x * 128;

    const uint4* A4h = (const uint4*)Ahi;
    const uint4* A4l = (const uint4*)Alo;
    const uint4* B4h = (const uint4*)Bhi;
    const uint4* B4l = (const uint4*)Blo;

    float acc[2][8][4];
    #pragma unroll
    for (int mt = 0; mt < 2; mt++)
        #pragma unroll
        for (int nt = 0; nt < 8; nt++)
            #pragma unroll
            for (int q = 0; q < 4; q++) acc[mt][nt][q] = 0.f;

    for (int s = 0; s < 8; s++) {
        uint4 va[2], vb[2], vc[2], vd[2];
        #pragma unroll
        for (int i = 0; i < 2; i++) {
            int f = tid + i*256;          // 0..511
            int r = f >> 2, q = f & 3;
            va[i] = A4h[(size_t)(row0 + r)*32 + s*4 + q];
            vb[i] = A4l[(size_t)(row0 + r)*32 + s*4 + q];
            vc[i] = B4h[(size_t)(col0 + r)*32 + s*4 + q];
            vd[i] = B4l[(size_t)(col0 + r)*32 + s*4 + q];
        }
        __syncthreads();   // previous slab's compute done
        #pragma unroll
        for (int i = 0; i < 2; i++) {
            int f = tid + i*256;
            int r = f >> 2, q = f & 3;
            *(uint2*)&sAh[r][q*8]     = make_uint2(va[i].x, va[i].y);
            *(uint2*)&sAh[r][q*8 + 4] = make_uint2(va[i].z, va[i].w);
            *(uint2*)&sAl[r][q*8]     = make_uint2(vb[i].x, vb[i].y);
            *(uint2*)&sAl[r][q*8 + 4] = make_uint2(vb[i].z, vb[i].w);
            *(uint2*)&sBh[r][q*8]     = make_uint2(vc[i].x, vc[i].y);
            *(uint2*)&sBh[r][q*8 + 4] = make_uint2(vc[i].z, vc[i].w);
            *(uint2*)&sBl[r][q*8]     = make_uint2(vd[i].x, vd[i].y);
            *(uint2*)&sBl[r][q*8 + 4] = make_uint2(vd[i].z, vd[i].w);
        }
        __syncthreads();

        #pragma unroll
        for (int kk = 0; kk < 32; kk += 16) {
            uint32_t ah[2][4], al[2][4];
            #pragma unroll
            for (int mt = 0; mt < 2; mt++) {
                int rb = wm + mt*16;
                ah[mt][0] = *(const uint32_t*)&sAh[rb + g    ][kk + tig*2];
                ah[mt][1] = *(const uint32_t*)&sAh[rb + g + 8][kk + tig*2];
                ah[mt][2] = *(const uint32_t*)&sAh[rb + g    ][kk + 8 + tig*2];
                ah[mt][3] = *(const uint32_t*)&sAh[rb + g + 8][kk + 8 + tig*2];
                al[mt][0] = *(const uint32_t*)&sAl[rb + g    ][kk + tig*2];
                al[mt][1] = *(const uint32_t*)&sAl[rb + g + 8][kk + tig*2];
                al[mt][2] = *(const uint32_t*)&sAl[rb + g    ][kk + 8 + tig*2];
                al[mt][3] = *(const uint32_t*)&sAl[rb + g + 8][kk + 8 + tig*2];
            }
            #pragma unroll
            for (int nt = 0; nt < 8; nt++) {
                int nb = wn + nt*8 + g;
                uint32_t bh0 = *(const uint32_t*)&sBh[nb][kk + tig*2];
                uint32_t bh1 = *(const uint32_t*)&sBh[nb][kk + 8 + tig*2];
                uint32_t bl0 = *(const uint32_t*)&sBl[nb][kk + tig*2];
                uint32_t bl1 = *(const uint32_t*)&sBl[nb][kk + 8 + tig*2];
                #pragma unroll
                for (int mt = 0; mt < 2; mt++) {
                    MMA16816(acc[mt][nt], ah[mt][0], ah[mt][1], ah[mt][2], ah[mt][3], bh0, bh1);
                    MMA16816(acc[mt][nt], ah[mt][0], ah[mt][1], ah[mt][2], ah[mt][3], bl0, bl1);
                    MMA16816(acc[mt][nt], al[mt][0], al[mt][1], al[mt][2], al[mt][3], bh0, bh1);
                }
            }
        }
    }

    #pragma unroll
    for (int mt = 0; mt < 2; mt++) {
        int r0 = row0 + wm + mt*16 + g;
        #pragma unroll
        for (int nt = 0; nt < 8; nt++) {
            int c0 = col0 + wn + nt*8 + tig*2;
            *(float2*)&C[(size_t)r0*N + c0]       = make_float2(acc[mt][nt][0], acc[mt][nt][1]);
            *(float2*)&C[(size_t)(r0 + 8)*N + c0] = make_float2(acc[mt][nt][2], acc[mt][nt][3]);
        }
    }
}

// ---------------- weight transpose + split ----------------
__global__ void concat_split_kernel(const float* __restrict__ W,  const float* __restrict__ Wz,
                                    const float* __restrict__ Uz, const float* __restrict__ Wr,
                                    const float* __restrict__ Ur, const float* __restrict__ Wn,
                                    const float* __restrict__ Un) {
    int i = blockIdx.x * blockDim.x + threadIdx.x;
    if (i >= 256*256) return;
    int k = i >> 8, j = i & 255;
    bsplit(W[i],  &g_WT_hi[j*256 + k],          &g_WT_lo[j*256 + k]);
    bsplit(Wz[i], &g_WcatT_hi[j*256 + k],       &g_WcatT_lo[j*256 + k]);
    bsplit(Wr[i], &g_WcatT_hi[(j+256)*256 + k], &g_WcatT_lo[(j+256)*256 + k]);
    bsplit(Wn[i], &g_WcatT_hi[(j+512)*256 + k], &g_WcatT_lo[(j+512)*256 + k]);
    bsplit(Uz[i], &g_UcatT_hi[j*256 + k],       &g_UcatT_lo[j*256 + k]);
    bsplit(Ur[i], &g_UcatT_hi[(j+256)*256 + k], &g_UcatT_lo[(j+256)*256 + k]);
    bsplit(Un[i], &g_UnT_hi[j*256 + k],         &g_UnT_lo[j*256 + k]);
}

// ---------------- h init + split ----------------
__global__ void init_kernel(const float* __restrict__ emb, const float* __restrict__ nmask,
                            const int* __restrict__ nodeidx) {
    int idx = blockIdx.x * blockDim.x + threadIdx.x;
    if (idx >= NTOT*NHID) return;
    int v = idx >> 8, d = idx & 255;
    int s = nodeidx[v];
    float h = emb[s*NFEAT + d] * nmask[s];
    g_h[idx] = h;
    bsplit(h, &g_h_hi[idx], &g_h_lo[idx]);
}

// ---------------- CSR build ----------------
__global__ void zero_cnt_kernel() {
    int i = blockIdx.x * blockDim.x + threadIdx.x;
    if (i < NTOT) g_cnt[i] = 0;
}
__global__ void count_kernel(const int* __restrict__ dst) {
    int e = blockIdx.x * blockDim.x + threadIdx.x;
    if (e < EDGES) atomicAdd(&g_cnt[dst[e]], 1);
}
__global__ void scan_kernel() {
    __shared__ int s[1024];
    __shared__ int carry;
    int tid = threadIdx.x;
    if (tid == 0) { carry = 0; g_off[0] = 0; }
    __syncthreads();
    for (int c = 0; c < NTOT/1024; c++) {
        int i = c*1024 + tid;
        s[tid] = g_cnt[i];
        __syncthreads();
        for (int d = 1; d < 1024; d <<= 1) {
            int t = (tid >= d) ? s[tid-d] : 0;
            __syncthreads();
            s[tid] += t;
            __syncthreads();
        }
        g_off[i+1] = carry + s[tid];
        __syncthreads();
        if (tid == 0) carry += s[1023];
        __syncthreads();
    }
}
__global__ void fill_kernel() {
    int i = blockIdx.x * blockDim.x + threadIdx.x;
    if (i < NTOT) g_fill[i] = g_off[i];
}
__global__ void scatter_kernel(const int* __restrict__ src, const int* __restrict__ dst) {
    int e = blockIdx.x * blockDim.x + threadIdx.x;
    if (e >= EDGES) return;
    int p = atomicAdd(&g_fill[dst[e]], 1);
    g_csr[p] = src[e];
}

// ---------------- es/ed dots ----------------
__global__ void esed_kernel(const float* __restrict__ a_src, const float* __restrict__ a_dst,
                            int nW, int stride, int off) {
    int w = (blockIdx.x * blockDim.x + threadIdx.x) >> 5;
    if (w >= nW) return;
    int node = (w >> 7)*stride + off + (w & 127);
    int lane = threadIdx.x & 31;
    int head = lane >> 3;
    int dbase = lane * 8;
    const float4* wh = (const float4*)&g_Wh[node*NHID + dbase];
    const float4* as = (const float4*)&a_src[dbase];
    const float4* ad = (const float4*)&a_dst[dbase];
    float4 w0 = wh[0], w1 = wh[1];
    float4 s0 = as[0], s1 = as[1];
    float4 d0 = ad[0], d1 = ad[1];
    float ps = w0.x*s0.x + w0.y*s0.y + w0.z*s0.z + w0.w*s0.w
             + w1.x*s1.x + w1.y*s1.y + w1.z*s1.z + w1.w*s1.w;
    float pd = w0.x*d0.x + w0.y*d0.y + w0.z*d0.z + w0.w*d0.w
             + w1.x*d1.x + w1.y*d1.y + w1.z*d1.z + w1.w*d1.w;
    #pragma unroll
    for (int o = 4; o; o >>= 1) {
        ps += __shfl_xor_sync(0xffffffffu, ps, o);
        pd += __shfl_xor_sync(0xffffffffu, pd, o);
    }
    if ((lane & 7) == 0) {
        g_es[node*4 + head] = ps;
        g_ed[node*4 + head] = pd;
    }
}

// ---------------- edge kernel: warp per dst node ----------------
__global__ void edge_kernel(int nW, int stride, int off, int last) {
    int w = (blockIdx.x * blockDim.x + threadIdx.x) >> 5;
    if (w >= nW) return;
    int lane = threadIdx.x & 31;
    int node = last ? w : (w >> 7)*stride + off + (w & 127);
    int doMsg = last ? (((w >> 7) % TT) == TT-1) : 1;
    int beg = g_off[node], end = g_off[node+1];
    float4 edv = *(const float4*)&g_ed[node*4];

    float m0 = -1e30f, m1 = -1e30f, m2 = -1e30f, m3 = -1e30f;
    for (int i = beg + lane; i < end; i += 32) {
        int s = g_csr[i];
        float4 esv = *(const float4*)&g_es[s*4];
        m0 = fmaxf(m0, lrelu(esv.x + edv.x));
        m1 = fmaxf(m1, lrelu(esv.y + edv.y));
        m2 = fmaxf(m2, lrelu(esv.z + edv.z));
        m3 = fmaxf(m3, lrelu(esv.w + edv.w));
    }
    #pragma unroll
    for (int o = 16; o; o >>= 1) {
        m0 = fmaxf(m0, __shfl_xor_sync(0xffffffffu, m0, o));
        m1 = fmaxf(m1, __shfl_xor_sync(0xffffffffu, m1, o));
        m2 = fmaxf(m2, __shfl_xor_sync(0xffffffffu, m2, o));
        m3 = fmaxf(m3, __shfl_xor_sync(0xffffffffu, m3, o));
    }

    float d0 = 0.f, d1 = 0.f, d2 = 0.f, d3 = 0.f;
    for (int i = beg + lane; i < end; i += 32) {
        int s = g_csr[i];
        float4 esv = *(const float4*)&g_es[s*4];
        d0 += expf(lrelu(esv.x + edv.x) - m0);
        d1 += expf(lrelu(esv.y + edv.y) - m1);
        d2 += expf(lrelu(esv.z + edv.z) - m2);
        d3 += expf(lrelu(esv.w + edv.w) - m3);
    }
    #pragma unroll
    for (int o = 16; o; o >>= 1) {
        d0 += __shfl_xor_sync(0xffffffffu, d0, o);
        d1 += __shfl_xor_sync(0xffffffffu, d1, o);
        d2 += __shfl_xor_sync(0xffffffffu, d2, o);
        d3 += __shfl_xor_sync(0xffffffffu, d3, o);
    }
    float i0 = 1.f/(d0 + 1e-9f), i1 = 1.f/(d1 + 1e-9f);
    float i2 = 1.f/(d2 + 1e-9f), i3 = 1.f/(d3 + 1e-9f);

    if (last && lane == 0)
        g_ascore[node] = 0.25f * (d0*i0 + d1*i1 + d2*i2 + d3*i3);

    if (!doMsg) return;

    float acc[8];
    #pragma unroll
    for (int i = 0; i < 8; i++) acc[i] = 0.f;
    int head = lane >> 3;
    for (int s0 = beg; s0 < end; s0 += 32) {
        int i = s0 + lane;
        int src = 0;
        float a0 = 0.f, a1 = 0.f, a2 = 0.f, a3 = 0.f;
        if (i < end) {
            src = g_csr[i];
            float4 esv = *(const float4*)&g_es[src*4];
            a0 = expf(lrelu(esv.x + edv.x) - m0) * i0;
            a1 = expf(lrelu(esv.y + edv.y) - m1) * i1;
            a2 = expf(lrelu(esv.z + edv.z) - m2) * i2;
            a3 = expf(lrelu(esv.w + edv.w) - m3) * i3;
        }
        int cnt = end - s0; if (cnt > 32) cnt = 32;
        for (int j = 0; j < cnt; j++) {
            int sj = __shfl_sync(0xffffffffu, src, j);
            float b0 = __shfl_sync(0xffffffffu, a0, j);
            float b1 = __shfl_sync(0xffffffffu, a1, j);
            float b2 = __shfl_sync(0xffffffffu, a2, j);
            float b3 = __shfl_sync(0xffffffffu, a3, j);
            float aj = (head == 0) ? b0 : (head == 1) ? b1 : (head == 2) ? b2 : b3;
            const float4* wp = (const float4*)&g_Wh[sj*NHID + lane*8];
            float4 w0 = wp[0], w1 = wp[1];
            acc[0] = fmaf(aj, w0.x, acc[0]); acc[1] = fmaf(aj, w0.y, acc[1]);
            acc[2] = fmaf(aj, w0.z, acc[2]); acc[3] = fmaf(aj, w0.w, acc[3]);
            acc[4] = fmaf(aj, w1.x, acc[4]); acc[5] = fmaf(aj, w1.y, acc[5]);
            acc[6] = fmaf(aj, w1.z, acc[6]); acc[7] = fmaf(aj, w1.w, acc[7]);
        }
    }
    // write message as bf16 hi/lo split
    __nv_bfloat162* mh = (__nv_bfloat162*)&g_msg_hi[node*NHID + lane*8];
    __nv_bfloat162* ml = (__nv_bfloat162*)&g_msg_lo[node*NHID + lane*8];
    #pragma unroll
    for (int jj = 0; jj < 4; jj++) {
        float a = acc[2*jj], b = acc[2*jj+1];
        __nv_bfloat16 ah = __float2bfloat16(a), bh = __float2bfloat16(b);
        mh[jj] = __halves2bfloat162(ah, bh);
        ml[jj] = __halves2bfloat162(__float2bfloat16(a - __bfloat162float(ah)),
                                    __float2bfloat16(b - __bfloat162float(bh)));
    }
}

// ---------------- gates on turn-t rows ----------------
__global__ void gate_kernel(const float* __restrict__ bz, const float* __restrict__ br, int t) {
    int idx = blockIdx.x * blockDim.x + threadIdx.x;
    if (idx >= NSEL*NHID) return;
    int vl = idx >> 8, d = idx & 255;
    int v = (vl >> 7)*768 + t*128 + (vl & 127);
    float mz = g_gm[(size_t)v*768 + d],       mr = g_gm[(size_t)v*768 + 256 + d];
    float hz = g_gh[(size_t)v*512 + d],       hr = g_gh[(size_t)v*512 + 256 + d];
    float z = 1.f / (1.f + expf(-(mz + hz + bz[d])));
    float r = 1.f / (1.f + expf(-(mr + hr + br[d])));
    g_z[v*256 + d] = z;
    float rh = r * g_h[v*256 + d];
    bsplit(rh, &g_rh_hi[v*256 + d], &g_rh_lo[v*256 + d]);
}

// ---------------- GRU update on turn-t rows ----------------
__global__ void update_kernel(const float* __restrict__ bn, int t) {
    int idx = blockIdx.x * blockDim.x + threadIdx.x;
    if (idx >= NSEL*NHID) return;
    int vl = idx >> 8, d = idx & 255;
    int v = (vl >> 7)*768 + t*128 + (vl & 127);
    float n = tanhf(g_gm[(size_t)v*768 + 512 + d] + g_rn[v*256 + d] + bn[d]);
    float z = g_z[v*256 + d];
    float h = g_h[v*256 + d];
    float hn = (1.f - z) * h + z * n;
    g_h[v*256 + d] = hn;
    bsplit(hn, &g_h_hi[v*256 + d], &g_h_lo[v*256 + d]);
}

// ---------------- pooling ----------------
__global__ void pool_kernel() {
    __shared__ float sa[128];
    __shared__ float sred[256];
    int bt = blockIdx.x;
    int base = bt * NN;
    int tid = threadIdx.x;
    float sc = (tid < 128) ? g_ascore[base + tid] : -1e30f;
    sred[tid] = sc; __syncthreads();
    for (int s = 128; s > 0; s >>= 1) {
        if (tid < s) sred[tid] = fmaxf(sred[tid], sred[tid + s]);
        __syncthreads();
    }
    float mx = sred[0]; __syncthreads();
    float e = (tid < 128) ? expf(sc - mx) : 0.f;
    sred[tid] = e; __syncthreads();
    for (int s = 128; s > 0; s >>= 1) {
        if (tid < s) sred[tid] += sred[tid + s];
        __syncthreads();
    }
    float tot = sred[0];
    if (tid < 128) sa[tid] = e / tot;
    __syncthreads();
    float acc = 0.f;
    for (int n = 0; n < NN; n++)
        acc = fmaf(g_h[(base + n)*NHID + tid], sa[n], acc);
    g_pooled[bt*NHID + tid] = acc * (1.f/128.f);
}

__global__ void out_kernel(float* __restrict__ out) {
    int i = blockIdx.x * blockDim.x + threadIdx.x;
    if (i >= BB*NHID) return;
    int b = i >> 8, d = i & 255;
    float r1 = g_pooled[(b*TT + 0)*NHID + d] + g_pooled[(b*TT + 2)*NHID + d] + g_pooled[(b*TT + 4)*NHID + d];
    float r2 = g_pooled[(b*TT + 1)*NHID + d] + g_pooled[(b*TT + 3)*NHID + d] + g_pooled[(b*TT + 5)*NHID + d];
    out[b*NHID + d] = r1;
    out[BB*NHID + b*NHID + d] = r2;
}

// ---------------- host ----------------
extern "C" void kernel_launch(void* const* d_in, const int* in_sizes, int n_in,
                              void* d_out, int out_size) {
    const float* emb    = (const float*)d_in[0];
    const float* nmask  = (const float*)d_in[1];
    const float* W      = (const float*)d_in[2];
    const float* a_src  = (const float*)d_in[3];
    const float* a_dst  = (const float*)d_in[4];
    const float* Wz     = (const float*)d_in[5];
    const float* Uz     = (const float*)d_in[6];
    const float* Wr     = (const float*)d_in[7];
    const float* Ur     = (const float*)d_in[8];
    const float* Wn     = (const float*)d_in[9];
    const float* Un     = (const float*)d_in[10];
    const float* bz     = (const float*)d_in[11];
    const float* br     = (const float*)d_in[12];
    const float* bn     = (const float*)d_in[13];
    const int*   nodeidx= (const int*)d_in[14];
    const int*   esrc   = (const int*)d_in[15];
    const int*   edst   = (const int*)d_in[16];
    float* out = (float*)d_out;

    float *p_Wh, *p_gm, *p_gh, *p_rn;
    __nv_bfloat16 *p_hhi, *p_hlo, *p_mhi, *p_mlo, *p_rhi, *p_rlo;
    __nv_bfloat16 *p_WThi, *p_WTlo, *p_WcThi, *p_WcTlo, *p_UcThi, *p_UcTlo, *p_UnThi, *p_UnTlo;
    cudaGetSymbolAddress((void**)&p_Wh,    g_Wh);
    cudaGetSymbolAddress((void**)&p_gm,    g_gm);
    cudaGetSymbolAddress((void**)&p_gh,    g_gh);
    cudaGetSymbolAddress((void**)&p_rn,    g_rn);
    cudaGetSymbolAddress((void**)&p_hhi,   g_h_hi);
    cudaGetSymbolAddress((void**)&p_hlo,   g_h_lo);
    cudaGetSymbolAddress((void**)&p_mhi,   g_msg_hi);
    cudaGetSymbolAddress((void**)&p_mlo,   g_msg_lo);
    cudaGetSymbolAddress((void**)&p_rhi,   g_rh_hi);
    cudaGetSymbolAddress((void**)&p_rlo,   g_rh_lo);
    cudaGetSymbolAddress((void**)&p_WThi,  g_WT_hi);
    cudaGetSymbolAddress((void**)&p_WTlo,  g_WT_lo);
    cudaGetSymbolAddress((void**)&p_WcThi, g_WcatT_hi);
    cudaGetSymbolAddress((void**)&p_WcTlo, g_WcatT_lo);
    cudaGetSymbolAddress((void**)&p_UcThi, g_UcatT_hi);
    cudaGetSymbolAddress((void**)&p_UcTlo, g_UcatT_lo);
    cudaGetSymbolAddress((void**)&p_UnThi, g_UnT_hi);
    cudaGetSymbolAddress((void**)&p_UnTlo, g_UnT_lo);

    // prep
    concat_split_kernel<<<256, 256>>>(W, Wz, Uz, Wr, Ur, Wn, Un);
    init_kernel<<<(NTOT*NHID)/256, 256>>>(emb, nmask, nodeidx);
    zero_cnt_kernel<<<48, 256>>>();
    count_kernel<<<EDGES/256, 256>>>(edst);
    scan_kernel<<<1, 1024>>>();
    fill_kernel<<<48, 256>>>();
    scatter_kernel<<<EDGES/256, 256>>>(esrc, edst);

    const int fullWarpBlocks = (NTOT*32)/256;   // 1536
    const int selWarpBlocks  = (NSEL*32)/256;   // 256

    // full Wh = h @ W  and full gh = h @ [Uz|Ur]  (turn-t rows keep initial h until turn t)
    mma_gemm<<<dim3(2, 96), 256>>>(p_hhi, p_hlo, p_WThi, p_WTlo, p_Wh, 256, 128, 0);
    esed_kernel<<<fullWarpBlocks, 256>>>(a_src, a_dst, NTOT, 128, 0);
    mma_gemm<<<dim3(4, 96), 256>>>(p_hhi, p_hlo, p_UcThi, p_UcTlo, p_gh, 512, 128, 0);

    for (int t = 0; t < TT; t++) {
        if (t > 0) {
            // refresh Wh / es / ed for rows of turn t-1 (the only changed h rows)
            mma_gemm<<<dim3(2, BB), 256>>>(p_hhi, p_hlo, p_WThi, p_WTlo, p_Wh, 256, 768, (t-1)*128);
            esed_kernel<<<selWarpBlocks, 256>>>(a_src, a_dst, NSEL, 768, (t-1)*128);
        }
        if (t == TT-1) {
            edge_kernel<<<fullWarpBlocks, 256>>>(NTOT, 128, 0, 1);
        } else {
            edge_kernel<<<selWarpBlocks, 256>>>(NSEL, 768, t*128, 0);
        }
        // gm = msg @ [Wz|Wr|Wn]  (turn-t rows)
        mma_gemm<<<dim3(6, BB), 256>>>(p_mhi, p_mlo, p_WcThi, p_WcTlo, p_gm, 768, 768, t*128);
        gate_kernel<<<(NSEL*NHID)/256, 256>>>(bz, br, t);
        // rn = (r*h) @ Un  (turn-t rows)
        mma_gemm<<<dim3(2, BB), 256>>>(p_rhi, p_rlo, p_UnThi, p_UnTlo, p_rn, 256, 768, t*128);
        update_kernel<<<(NSEL*NHID)/256, 256>>>(bn, t);
    }

    pool_kernel<<<BB*TT, 256>>>();
    out_kernel<<<BB*NHID/256, 256>>>(out);
    (void)in_sizes; (void)n_in; (void)out_size;
}